// round 15
// baseline (speedup 1.0000x reference)
#include <cuda_runtime.h>
#include <cuda_fp16.h>
#include <cstdint>
#include <math.h>

#define DIMX   1536
#define QKVD   4608
#define NHEADS 24
#define HDIM   64
#define BB     2
#define NXX    2048
#define NCC    256
#define NTOTAL 2304
#define SCALE_LOG2E 0.18033688011112042f   // 0.125 * log2(e)

// ---------------- fp16 scratch (device globals; no allocation) -------------
__device__ __half g_hx[(size_t)BB*NXX*DIMX];
__device__ __half g_hc[(size_t)BB*NCC*DIMX];
__device__ __half g_hWqx[(size_t)QKVD*DIMX];
__device__ __half g_hWqc[(size_t)QKVD*DIMX];
__device__ __half g_hWpx[(size_t)DIMX*DIMX];
__device__ __half g_hWpc[(size_t)DIMX*DIMX];
__device__ __half g_q[(size_t)BB*NHEADS*NTOTAL*HDIM];   // holds q * SCALE_LOG2E
__device__ __half g_k[(size_t)BB*NHEADS*NTOTAL*HDIM];
__device__ __half g_v[(size_t)BB*NHEADS*NTOTAL*HDIM];
__device__ __half g_o[(size_t)BB*NHEADS*NTOTAL*HDIM];

// ---------------- helpers ----------------
__device__ __forceinline__ uint32_t s2u(const void* p) {
    return (uint32_t)__cvta_generic_to_shared(p);
}
__device__ __forceinline__ void cp16(uint32_t dst, const void* src) {
    asm volatile("cp.async.cg.shared.global [%0], [%1], 16;" :: "r"(dst), "l"(src));
}
#define CP_COMMIT() asm volatile("cp.async.commit_group;" ::: "memory")
#define CP_WAIT0()  asm volatile("cp.async.wait_group 0;" ::: "memory")
#define CP_WAIT1()  asm volatile("cp.async.wait_group 1;" ::: "memory")
#define CP_WAIT2()  asm volatile("cp.async.wait_group 2;" ::: "memory")

__device__ __forceinline__ float ex2(float x) {
    float r;
    asm("ex2.approx.f32 %0, %1;" : "=f"(r) : "f"(x));
    return r;
}
__device__ __forceinline__ void ldsm4(uint32_t& r0, uint32_t& r1, uint32_t& r2,
                                      uint32_t& r3, uint32_t addr) {
    asm volatile("ldmatrix.sync.aligned.m8n8.x4.shared.b16 {%0,%1,%2,%3}, [%4];"
                 : "=r"(r0), "=r"(r1), "=r"(r2), "=r"(r3) : "r"(addr));
}
__device__ __forceinline__ void ldsm4t(uint32_t& r0, uint32_t& r1, uint32_t& r2,
                                       uint32_t& r3, uint32_t addr) {
    asm volatile("ldmatrix.sync.aligned.m8n8.x4.trans.shared.b16 {%0,%1,%2,%3}, [%4];"
                 : "=r"(r0), "=r"(r1), "=r"(r2), "=r"(r3) : "r"(addr));
}
__device__ __forceinline__ void mma_f16(float* d, const uint32_t* a,
                                        uint32_t b0, uint32_t b1) {
    asm volatile(
        "mma.sync.aligned.m16n8k16.row.col.f32.f16.f16.f32 "
        "{%0,%1,%2,%3}, {%4,%5,%6,%7}, {%8,%9}, {%0,%1,%2,%3};"
        : "+f"(d[0]), "+f"(d[1]), "+f"(d[2]), "+f"(d[3])
        : "r"(a[0]), "r"(a[1]), "r"(a[2]), "r"(a[3]), "r"(b0), "r"(b1));
}

// ---------------- merged fp32 -> fp16 conversion ----------------
#define F4_NX  ((BB*NXX*DIMX) / 4)
#define F4_NC  ((BB*NCC*DIMX) / 4)
#define F4_WQ  ((QKVD*DIMX) / 4)
#define F4_WP  ((DIMX*DIMX) / 4)
#define F4_TOT (F4_NX + F4_NC + 2*F4_WQ + 2*F4_WP)

__global__ __launch_bounds__(256) void f2h_all_kernel(
    const float* __restrict__ x, const float* __restrict__ c,
    const float* __restrict__ wqx, const float* __restrict__ wqc,
    const float* __restrict__ wpx, const float* __restrict__ wpc)
{
    int i = blockIdx.x * 256 + threadIdx.x;
    if (i >= F4_TOT) return;
    const float* s; __half* d; int off;
    if (i < F4_NX)                          { s = x;   d = g_hx;  off = i; }
    else if (i < F4_NX + F4_NC)             { s = c;   d = g_hc;  off = i - F4_NX; }
    else if (i < F4_NX + F4_NC + F4_WQ)     { s = wqx; d = g_hWqx; off = i - F4_NX - F4_NC; }
    else if (i < F4_NX + F4_NC + 2*F4_WQ)   { s = wqc; d = g_hWqc; off = i - F4_NX - F4_NC - F4_WQ; }
    else if (i < F4_NX + F4_NC + 2*F4_WQ + F4_WP)
                                            { s = wpx; d = g_hWpx; off = i - F4_NX - F4_NC - 2*F4_WQ; }
    else                                    { s = wpc; d = g_hWpc; off = i - F4_NX - F4_NC - 2*F4_WQ - F4_WP; }
    float4 v = *(const float4*)(s + (size_t)off * 4);
    __half2* dp = (__half2*)(d + (size_t)off * 4);
    dp[0] = __floats2half2_rn(v.x, v.y);
    dp[1] = __floats2half2_rn(v.z, v.w);
}

// ======================= fp16 tensor-core GEMM =======================
#define GK      32
#define GROWB   80
#define GOP_BYTES (128 * GROWB)
#define GSTAGE  (2 * GOP_BYTES)
#define GEMM_SMEM (4 * GSTAGE)
#define GNITER  (DIMX / GK)

template<int MODE>
__global__ __launch_bounds__(256, 2) void gemm_h_kernel(
    const __half* __restrict__ A0, const __half* __restrict__ A1,
    const __half* __restrict__ W0, const __half* __restrict__ W1,
    const float* __restrict__ b0, const float* __restrict__ b1,
    float* __restrict__ out, int rowsX)
{
    extern __shared__ char dsm[];
    const uint32_t smem0 = s2u(dsm);
    const int tid = threadIdx.x;
    const int w = tid >> 5, lane = tid & 31;
    const int qg = lane >> 2, qt = lane & 3;
    const int mi = lane >> 3, ri = lane & 7;
    const int mbase = (w & 3) * 32, nbase = (w >> 2) * 64;

    const int by = blockIdx.y;
    const bool isC = (by >= rowsX);
    const __half* A  = isC ? A1 : A0;
    const __half* Wt = isC ? W1 : W0;
    const float* bias = isC ? b1 : b0;
    const int Nt    = isC ? NCC : NXX;
    const int n_off = isC ? NXX : 0;
    const int rowBase = (isC ? (by - rowsX) : by) * 128;
    const int colBase = blockIdx.x * 128;
    float* outf = (MODE == 1) ? (out + (isC ? (size_t)BB * NXX * DIMX : 0)) : out;

    const __half* asrc[2];
    const __half* wsrc[2];
    uint32_t dsto[2];
    int chh[2];
#pragma unroll
    for (int j = 0; j < 2; j++) {
        int slot = tid + j * 256;
        int r = slot >> 2, ch = slot & 3;
        dsto[j] = (uint32_t)(r * GROWB + ch * 16);
        chh[j] = ch;
        wsrc[j] = Wt + (size_t)(colBase + r) * DIMX;
        if (MODE == 0) {
            asrc[j] = A + (size_t)(rowBase + r) * DIMX;
        } else {
            int row = rowBase + r;
            int bi = row / Nt;
            int n = row - bi * Nt;
            asrc[j] = g_o + ((size_t)bi * NHEADS * NTOTAL + n_off + n) * HDIM;
        }
    }

    auto issue = [&](int it) {
        if (it < GNITER) {
            const int k0 = it * GK;
            const uint32_t sa = smem0 + (it & 3) * GSTAGE;
            const uint32_t sb = sa + GOP_BYTES;
#pragma unroll
            for (int j = 0; j < 2; j++) {
                const __half* s;
                if (MODE == 0) {
                    s = asrc[j] + k0 + chh[j] * 8;
                } else {
                    int h = k0 >> 6;
                    int d = (k0 & 63) + chh[j] * 8;
                    s = asrc[j] + (size_t)h * (NTOTAL * HDIM) + d;
                }
                cp16(sa + dsto[j], s);
                cp16(sb + dsto[j], wsrc[j] + k0 + chh[j] * 8);
            }
        }
        CP_COMMIT();
    };

    float acc[2][8][4];
#pragma unroll
    for (int mf = 0; mf < 2; mf++)
#pragma unroll
        for (int nf = 0; nf < 8; nf++)
#pragma unroll
            for (int e = 0; e < 4; e++) acc[mf][nf][e] = 0.f;

    issue(0); issue(1); issue(2);
    for (int it = 0; it < GNITER; it++) {
        CP_WAIT2();
        __syncthreads();
        issue(it + 3);
        const uint32_t sa = smem0 + (it & 3) * GSTAGE;
        const uint32_t sb = sa + GOP_BYTES;
#pragma unroll
        for (int kc = 0; kc < 2; kc++) {
            const int kcb = kc * 32;
            uint32_t a[2][4], b[8][2];
#pragma unroll
            for (int mf = 0; mf < 2; mf++) {
                uint32_t ad = sa + (uint32_t)((mbase + mf * 16 + (mi & 1) * 8 + ri) * GROWB
                                              + kcb + (mi >> 1) * 16);
                ldsm4(a[mf][0], a[mf][1], a[mf][2], a[mf][3], ad);
            }
#pragma unroll
            for (int np = 0; np < 4; np++) {
                uint32_t bd = sb + (uint32_t)((nbase + np * 16 + (mi >> 1) * 8 + ri) * GROWB
                                              + kcb + (mi & 1) * 16);
                uint32_t r0, r1, r2, r3;
                ldsm4(r0, r1, r2, r3, bd);
                b[2 * np][0] = r0; b[2 * np][1] = r1;
                b[2 * np + 1][0] = r2; b[2 * np + 1][1] = r3;
            }
#pragma unroll
            for (int mf = 0; mf < 2; mf++)
#pragma unroll
                for (int nf = 0; nf < 8; nf++)
                    mma_f16(acc[mf][nf], a[mf], b[nf][0], b[nf][1]);
        }
    }

#pragma unroll
    for (int mf = 0; mf < 2; mf++) {
#pragma unroll
        for (int er = 0; er < 2; er++) {
            int r = rowBase + mbase + mf * 16 + qg + er * 8;
            if (MODE == 0) {
                int bi = r / Nt;
                int n = r - bi * Nt;
#pragma unroll
                for (int nf = 0; nf < 8; nf++) {
                    int cidx = colBase + nbase + nf * 8 + 2 * qt;
                    float v0 = acc[mf][nf][er * 2 + 0] + bias[cidx];
                    float v1 = acc[mf][nf][er * 2 + 1] + bias[cidx + 1];
                    int three = cidx / DIMX;
                    int rem = cidx - three * DIMX;
                    int h = rem >> 6, d = rem & 63;
                    if (three == 0) {           // q: pre-scale into exp2 domain
                        v0 *= SCALE_LOG2E;
                        v1 *= SCALE_LOG2E;
                    }
                    __half* dst = (three == 0) ? g_q : (three == 1) ? g_k : g_v;
                    *(__half2*)(dst + (((size_t)bi * NHEADS + h) * NTOTAL + (n_off + n)) * HDIM + d)
                        = __floats2half2_rn(v0, v1);
                }
            } else {
#pragma unroll
                for (int nf = 0; nf < 8; nf++) {
                    int cidx = colBase + nbase + nf * 8 + 2 * qt;
                    float v0 = acc[mf][nf][er * 2 + 0] + bias[cidx];
                    float v1 = acc[mf][nf][er * 2 + 1] + bias[cidx + 1];
                    *(float2*)(outf + (size_t)r * DIMX + cidx) = make_float2(v0, v1);
                }
            }
        }
    }
}

// ======================= fp16 flash attention =======================
// Br=128 (8 warps x 16 rows), Bc=64. 3-buffer K/V ring, ONE barrier per tile,
// 2-tile-deep cp.async prefetch. S pre-scaled (q carries SCALE*log2e).
// P packed directly into PV A-fragment registers; exp via ex2.approx.f16x2.
#define AROWB 144
#define AQ_BYTES  (128 * AROWB)       // 18432
#define AKV_BYTES (64 * AROWB)        // 9216
#define ANT      (NTOTAL / 64)        // 36 tiles
#define ATT_SMEM (AQ_BYTES + 6 * AKV_BYTES)   // 73728

__global__ __launch_bounds__(256, 2) void attn_h_kernel()
{
    extern __shared__ char dsm[];
    const uint32_t Qb = s2u(dsm);
    const uint32_t KV0 = Qb + AQ_BYTES;

    const int tid = threadIdx.x;
    const int w = tid >> 5, lane = tid & 31;
    const int qg = lane >> 2, qt = lane & 3;
    const int mi = lane >> 3, ri = lane & 7;
    const int h = blockIdx.y, bi = blockIdx.z;
    const size_t headbase = ((size_t)bi * NHEADS + h) * NTOTAL;
    const int qbase = blockIdx.x * 128;
    const int mrow = w * 16;

    // tile t lives in ring slot t%3: K at KV0 + slot*2*AKV, V at +AKV
    auto issue_tile = [&](int t) {
        if (t < ANT) {
            const int jt = t * 64;
            const uint32_t kb = KV0 + (uint32_t)(t % 3) * (2 * AKV_BYTES);
            const uint32_t vb = kb + AKV_BYTES;
#pragma unroll
            for (int i = 0; i < 2; i++) {
                int slot = tid + i * 256;
                int r = slot >> 3, ch = slot & 7;
                uint32_t off = (uint32_t)(r * AROWB + ch * 16);
                cp16(kb + off, g_k + (headbase + jt + r) * HDIM + ch * 8);
                cp16(vb + off, g_v + (headbase + jt + r) * HDIM + ch * 8);
            }
        }
        CP_COMMIT();   // empty group past the end keeps wait counts uniform
    };

    issue_tile(0);
    issue_tile(1);

    // stage Q (fp16): 128 rows x 8 chunks
    {
        __half* Qp = (__half*)dsm;
#pragma unroll
        for (int i = 0; i < 4; i++) {
            int slot = tid + i * 256;
            int r = slot >> 3, ch = slot & 7;
            uint4 t = *(const uint4*)(g_q + (headbase + qbase + r) * HDIM + ch * 8);
            *(uint4*)(Qp + r * 72 + ch * 8) = t;
        }
    }
    __syncthreads();

    uint32_t qf[4][4];
#pragma unroll
    for (int kf = 0; kf < 4; kf++) {
        uint32_t ad = Qb + (uint32_t)((mrow + (mi & 1) * 8 + ri) * AROWB
                                      + kf * 32 + (mi >> 1) * 16);
        ldsm4(qf[kf][0], qf[kf][1], qf[kf][2], qf[kf][3], ad);
    }

    float of[8][4];
#pragma unroll
    for (int nf = 0; nf < 8; nf++)
#pragma unroll
        for (int e = 0; e < 4; e++) of[nf][e] = 0.f;
    float m0 = -1e30f, m1 = -1e30f, l0 = 0.f, l1 = 0.f;

    for (int t = 0; t < ANT; t++) {
        CP_WAIT1();          // tile t's data complete (t+1 may remain in flight)
        __syncthreads();     // cross-thread visibility + ring-slot reuse safety
        issue_tile(t + 2);   // into slot (t+2)%3 == (t-1)%3: readers done (barrier)

        const uint32_t Kc = KV0 + (uint32_t)(t % 3) * (2 * AKV_BYTES);
        const uint32_t Vc = Kc + AKV_BYTES;

        // S = Q K^T (already scaled: q carries SCALE*log2e)
        float sf[8][4];
#pragma unroll
        for (int nf = 0; nf < 8; nf++)
#pragma unroll
            for (int e = 0; e < 4; e++) sf[nf][e] = 0.f;
#pragma unroll
        for (int kf = 0; kf < 4; kf++) {
            const int dcb = kf * 32;
#pragma unroll
            for (int np = 0; np < 4; np++) {
                uint32_t kd = Kc + (uint32_t)((np * 16 + (mi >> 1) * 8 + ri) * AROWB
                                              + dcb + (mi & 1) * 16);
                uint32_t r0, r1, r2, r3;
                ldsm4(r0, r1, r2, r3, kd);
                mma_f16(sf[2 * np], qf[kf], r0, r1);
                mma_f16(sf[2 * np + 1], qf[kf], r2, r3);
            }
        }

        // row max (per-quad)
        float mx0 = -1e30f, mx1 = -1e30f;
#pragma unroll
        for (int nf = 0; nf < 8; nf++) {
            mx0 = fmaxf(mx0, fmaxf(sf[nf][0], sf[nf][1]));
            mx1 = fmaxf(mx1, fmaxf(sf[nf][2], sf[nf][3]));
        }
        mx0 = fmaxf(mx0, __shfl_xor_sync(0xffffffffu, mx0, 1));
        mx0 = fmaxf(mx0, __shfl_xor_sync(0xffffffffu, mx0, 2));
        mx1 = fmaxf(mx1, __shfl_xor_sync(0xffffffffu, mx1, 1));
        mx1 = fmaxf(mx1, __shfl_xor_sync(0xffffffffu, mx1, 2));

        // rescale only when some lane's max moved (warp-uniform branch)
        unsigned ball = __ballot_sync(0xffffffffu, (mx0 <= m0) && (mx1 <= m1));
        if (ball != 0xffffffffu) {
            float nm0 = fmaxf(m0, mx0), nm1 = fmaxf(m1, mx1);
            float corr0 = ex2(m0 - nm0), corr1 = ex2(m1 - nm1);
#pragma unroll
            for (int nf = 0; nf < 8; nf++) {
                of[nf][0] *= corr0; of[nf][1] *= corr0;
                of[nf][2] *= corr1; of[nf][3] *= corr1;
            }
            l0 *= corr0; l1 *= corr1;
            m0 = nm0; m1 = nm1;
        }

        // exp + pack directly into PV A-fragments; accumulate l in fp32
        float s0 = 0.f, s1 = 0.f;
        uint32_t pfrag[4][4];
#pragma unroll
        for (int nf = 0; nf < 8; nf++) {
            __half2 e01 = h2exp2(__floats2half2_rn(sf[nf][0] - m0, sf[nf][1] - m0));
            __half2 e23 = h2exp2(__floats2half2_rn(sf[nf][2] - m1, sf[nf][3] - m1));
            float2 f01 = __half22float2(e01);
            float2 f23 = __half22float2(e23);
            s0 += f01.x + f01.y;
            s1 += f23.x + f23.y;
            pfrag[nf >> 1][((nf & 1) << 1) + 0] = *reinterpret_cast<uint32_t*>(&e01);
            pfrag[nf >> 1][((nf & 1) << 1) + 1] = *reinterpret_cast<uint32_t*>(&e23);
        }
        s0 += __shfl_xor_sync(0xffffffffu, s0, 1);
        s0 += __shfl_xor_sync(0xffffffffu, s0, 2);
        s1 += __shfl_xor_sync(0xffffffffu, s1, 1);
        s1 += __shfl_xor_sync(0xffffffffu, s1, 2);
        l0 += s0; l1 += s1;

        // O += P @ V (V via ldmatrix.trans; P already in A-frag registers)
#pragma unroll
        for (int jc = 0; jc < 4; jc++) {
#pragma unroll
            for (int np = 0; np < 4; np++) {
                uint32_t vd = Vc + (uint32_t)((jc * 16 + (mi & 1) * 8 + ri) * AROWB
                                              + np * 32 + (mi >> 1) * 16);
                uint32_t r0, r1, r2, r3;
                ldsm4t(r0, r1, r2, r3, vd);
                mma_f16(of[2 * np], pfrag[jc], r0, r1);
                mma_f16(of[2 * np + 1], pfrag[jc], r2, r3);
            }
        }
    }

    const float inv0 = 1.f / l0, inv1 = 1.f / l1;
    const int row0 = qbase + mrow + qg, row1 = row0 + 8;
#pragma unroll
    for (int nf = 0; nf < 8; nf++) {
        int col = nf * 8 + 2 * qt;
        *(__half2*)(g_o + (headbase + row0) * HDIM + col)
            = __floats2half2_rn(of[nf][0] * inv0, of[nf][1] * inv0);
        *(__half2*)(g_o + (headbase + row1) * HDIM + col)
            = __floats2half2_rn(of[nf][2] * inv1, of[nf][3] * inv1);
    }
}

// ---------------------------------------------------------------------------
extern "C" void kernel_launch(void* const* d_in, const int* in_sizes, int n_in,
                              void* d_out, int out_size)
{
    const float* x       = (const float*)d_in[0];
    const float* c       = (const float*)d_in[1];
    const float* Wqkv_x  = (const float*)d_in[2];
    const float* bqkv_x  = (const float*)d_in[3];
    const float* Wqkv_c  = (const float*)d_in[4];
    const float* bqkv_c  = (const float*)d_in[5];
    const float* Wproj_x = (const float*)d_in[6];
    const float* bproj_x = (const float*)d_in[7];
    const float* Wproj_c = (const float*)d_in[8];
    const float* bproj_c = (const float*)d_in[9];
    float* out = (float*)d_out;

    cudaFuncSetAttribute(gemm_h_kernel<0>,
                         cudaFuncAttributeMaxDynamicSharedMemorySize, GEMM_SMEM);
    cudaFuncSetAttribute(gemm_h_kernel<1>,
                         cudaFuncAttributeMaxDynamicSharedMemorySize, GEMM_SMEM);
    cudaFuncSetAttribute(attn_h_kernel,
                         cudaFuncAttributeMaxDynamicSharedMemorySize, ATT_SMEM);

    __half *hx, *hc, *hWqx, *hWqc, *hWpx, *hWpc;
    cudaGetSymbolAddress((void**)&hx,   g_hx);
    cudaGetSymbolAddress((void**)&hc,   g_hc);
    cudaGetSymbolAddress((void**)&hWqx, g_hWqx);
    cudaGetSymbolAddress((void**)&hWqc, g_hWqc);
    cudaGetSymbolAddress((void**)&hWpx, g_hWpx);
    cudaGetSymbolAddress((void**)&hWpc, g_hWpc);

    f2h_all_kernel<<<(F4_TOT + 255) / 256, 256>>>(x, c, Wqkv_x, Wqkv_c, Wproj_x, Wproj_c);

    gemm_h_kernel<0><<<dim3(QKVD / 128, (BB * NXX) / 128 + (BB * NCC) / 128),
                       256, GEMM_SMEM>>>(
        hx, hc, hWqx, hWqc, bqkv_x, bqkv_c, nullptr, (BB * NXX) / 128);

    attn_h_kernel<<<dim3(NTOTAL / 128, NHEADS, BB), 256, ATT_SMEM>>>();

    gemm_h_kernel<1><<<dim3(DIMX / 128, (BB * NXX) / 128 + (BB * NCC) / 128),
                       256, GEMM_SMEM>>>(
        nullptr, nullptr, hWpx, hWpc, bproj_x, bproj_c, out, (BB * NXX) / 128);
}

// round 16
// speedup vs baseline: 1.0482x; 1.0482x over previous
#include <cuda_runtime.h>
#include <cuda_fp16.h>
#include <cstdint>
#include <math.h>

#define DIMX   1536
#define QKVD   4608
#define NHEADS 24
#define HDIM   64
#define BB     2
#define NXX    2048
#define NCC    256
#define NTOTAL 2304
#define SCALE_LOG2E 0.18033688011112042f   // 0.125 * log2(e)

// ---------------- fp16 scratch (device globals; no allocation) -------------
__device__ __half g_hx[(size_t)BB*NXX*DIMX];
__device__ __half g_hc[(size_t)BB*NCC*DIMX];
__device__ __half g_hWqx[(size_t)QKVD*DIMX];
__device__ __half g_hWqc[(size_t)QKVD*DIMX];
__device__ __half g_hWpx[(size_t)DIMX*DIMX];
__device__ __half g_hWpc[(size_t)DIMX*DIMX];
__device__ __half g_q[(size_t)BB*NHEADS*NTOTAL*HDIM];   // holds q * SCALE_LOG2E
__device__ __half g_k[(size_t)BB*NHEADS*NTOTAL*HDIM];
__device__ __half g_v[(size_t)BB*NHEADS*NTOTAL*HDIM];
__device__ __half g_o[(size_t)BB*NHEADS*NTOTAL*HDIM];

// ---------------- helpers ----------------
__device__ __forceinline__ uint32_t s2u(const void* p) {
    return (uint32_t)__cvta_generic_to_shared(p);
}
__device__ __forceinline__ void cp16(uint32_t dst, const void* src) {
    asm volatile("cp.async.cg.shared.global [%0], [%1], 16;" :: "r"(dst), "l"(src));
}
#define CP_COMMIT() asm volatile("cp.async.commit_group;" ::: "memory")
#define CP_WAIT0()  asm volatile("cp.async.wait_group 0;" ::: "memory")
#define CP_WAIT1()  asm volatile("cp.async.wait_group 1;" ::: "memory")

__device__ __forceinline__ float ex2(float x) {
    float r;
    asm("ex2.approx.f32 %0, %1;" : "=f"(r) : "f"(x));
    return r;
}
__device__ __forceinline__ void ldsm4(uint32_t& r0, uint32_t& r1, uint32_t& r2,
                                      uint32_t& r3, uint32_t addr) {
    asm volatile("ldmatrix.sync.aligned.m8n8.x4.shared.b16 {%0,%1,%2,%3}, [%4];"
                 : "=r"(r0), "=r"(r1), "=r"(r2), "=r"(r3) : "r"(addr));
}
__device__ __forceinline__ void ldsm4t(uint32_t& r0, uint32_t& r1, uint32_t& r2,
                                       uint32_t& r3, uint32_t addr) {
    asm volatile("ldmatrix.sync.aligned.m8n8.x4.trans.shared.b16 {%0,%1,%2,%3}, [%4];"
                 : "=r"(r0), "=r"(r1), "=r"(r2), "=r"(r3) : "r"(addr));
}
__device__ __forceinline__ void mma_f16(float* d, const uint32_t* a,
                                        uint32_t b0, uint32_t b1) {
    asm volatile(
        "mma.sync.aligned.m16n8k16.row.col.f32.f16.f16.f32 "
        "{%0,%1,%2,%3}, {%4,%5,%6,%7}, {%8,%9}, {%0,%1,%2,%3};"
        : "+f"(d[0]), "+f"(d[1]), "+f"(d[2]), "+f"(d[3])
        : "r"(a[0]), "r"(a[1]), "r"(a[2]), "r"(a[3]), "r"(b0), "r"(b1));
}

// ---------------- merged fp32 -> fp16 conversion ----------------
#define F4_NX  ((BB*NXX*DIMX) / 4)
#define F4_NC  ((BB*NCC*DIMX) / 4)
#define F4_WQ  ((QKVD*DIMX) / 4)
#define F4_WP  ((DIMX*DIMX) / 4)
#define F4_TOT (F4_NX + F4_NC + 2*F4_WQ + 2*F4_WP)

__global__ __launch_bounds__(256) void f2h_all_kernel(
    const float* __restrict__ x, const float* __restrict__ c,
    const float* __restrict__ wqx, const float* __restrict__ wqc,
    const float* __restrict__ wpx, const float* __restrict__ wpc)
{
    int i = blockIdx.x * 256 + threadIdx.x;
    if (i >= F4_TOT) return;
    const float* s; __half* d; int off;
    if (i < F4_NX)                          { s = x;   d = g_hx;  off = i; }
    else if (i < F4_NX + F4_NC)             { s = c;   d = g_hc;  off = i - F4_NX; }
    else if (i < F4_NX + F4_NC + F4_WQ)     { s = wqx; d = g_hWqx; off = i - F4_NX - F4_NC; }
    else if (i < F4_NX + F4_NC + 2*F4_WQ)   { s = wqc; d = g_hWqc; off = i - F4_NX - F4_NC - F4_WQ; }
    else if (i < F4_NX + F4_NC + 2*F4_WQ + F4_WP)
                                            { s = wpx; d = g_hWpx; off = i - F4_NX - F4_NC - 2*F4_WQ; }
    else                                    { s = wpc; d = g_hWpc; off = i - F4_NX - F4_NC - 2*F4_WQ - F4_WP; }
    float4 v = *(const float4*)(s + (size_t)off * 4);
    __half2* dp = (__half2*)(d + (size_t)off * 4);
    dp[0] = __floats2half2_rn(v.x, v.y);
    dp[1] = __floats2half2_rn(v.z, v.w);
}

// ======================= fp16 tensor-core GEMM =======================
// K-tile 64 halves (24 iterations, HALF the barrier phases of GK=32).
// 3-stage cp.async ring, 144B padded rows, fragments via ldmatrix.
// MODE 0: A fp16 row-major, epilogue scatters half2 into g_q/g_k/g_v
//         (q is pre-scaled by SCALE_LOG2E)
// MODE 1: A gathered from g_o [B,H,N,D] fp16, epilogue fp32 +bias to out
#define GK      64
#define GROWB   144                   // bytes per padded row (64 halves + pad)
#define GOP_BYTES (128 * GROWB)       // 18432
#define GSTAGE  (2 * GOP_BYTES)       // 36864
#define GEMM_SMEM (3 * GSTAGE)        // 110592
#define GNITER  (DIMX / GK)           // 24

template<int MODE>
__global__ __launch_bounds__(256, 2) void gemm_h_kernel(
    const __half* __restrict__ A0, const __half* __restrict__ A1,
    const __half* __restrict__ W0, const __half* __restrict__ W1,
    const float* __restrict__ b0, const float* __restrict__ b1,
    float* __restrict__ out, int rowsX)
{
    extern __shared__ char dsm[];
    const uint32_t smem0 = s2u(dsm);
    const int tid = threadIdx.x;
    const int w = tid >> 5, lane = tid & 31;
    const int qg = lane >> 2, qt = lane & 3;
    const int mi = lane >> 3, ri = lane & 7;
    const int mbase = (w & 3) * 32, nbase = (w >> 2) * 64;

    const int by = blockIdx.y;
    const bool isC = (by >= rowsX);
    const __half* A  = isC ? A1 : A0;
    const __half* Wt = isC ? W1 : W0;
    const float* bias = isC ? b1 : b0;
    const int Nt    = isC ? NCC : NXX;
    const int n_off = isC ? NXX : 0;
    const int rowBase = (isC ? (by - rowsX) : by) * 128;
    const int colBase = blockIdx.x * 128;
    float* outf = (MODE == 1) ? (out + (isC ? (size_t)BB * NXX * DIMX : 0)) : out;

    // loader slots: 4 per thread per operand; each is one 16B chunk
    // stage layout: 128 rows x 8 data chunks (ch 0..7), row stride 144B
    const __half* asrc[4];
    const __half* wsrc[4];
    uint32_t dsto[4];
    int chh[4];
#pragma unroll
    for (int j = 0; j < 4; j++) {
        int slot = tid + j * 256;          // 0..1023
        int r = slot >> 3, ch = slot & 7;  // row 0..127, chunk 0..7
        dsto[j] = (uint32_t)(r * GROWB + ch * 16);
        chh[j] = ch;
        wsrc[j] = Wt + (size_t)(colBase + r) * DIMX;
        if (MODE == 0) {
            asrc[j] = A + (size_t)(rowBase + r) * DIMX;
        } else {
            int row = rowBase + r;
            int bi = row / Nt;
            int n = row - bi * Nt;
            asrc[j] = g_o + ((size_t)bi * NHEADS * NTOTAL + n_off + n) * HDIM;
        }
    }

    auto issue = [&](int it) {
        if (it < GNITER) {
            const int k0 = it * GK;        // multiple of 64
            const uint32_t sa = smem0 + (it % 3) * GSTAGE;
            const uint32_t sb = sa + GOP_BYTES;
#pragma unroll
            for (int j = 0; j < 4; j++) {
                const __half* s;
                if (MODE == 0) {
                    s = asrc[j] + k0 + chh[j] * 8;
                } else {
                    int h = k0 >> 6;               // k0 multiple of 64
                    int d = chh[j] * 8;            // 0..56 < 64
                    s = asrc[j] + (size_t)h * (NTOTAL * HDIM) + d;
                }
                cp16(sa + dsto[j], s);
                cp16(sb + dsto[j], wsrc[j] + k0 + chh[j] * 8);
            }
        }
        CP_COMMIT();   // empty group past the end keeps wait counts uniform
    };

    float acc[2][8][4];
#pragma unroll
    for (int mf = 0; mf < 2; mf++)
#pragma unroll
        for (int nf = 0; nf < 8; nf++)
#pragma unroll
            for (int e = 0; e < 4; e++) acc[mf][nf][e] = 0.f;

    issue(0); issue(1);
    for (int it = 0; it < GNITER; it++) {
        CP_WAIT1();          // tile it complete (it+1 may remain in flight)
        __syncthreads();
        issue(it + 2);       // slot (it+2)%3: its last reader was it-1, done
        const uint32_t sa = smem0 + (it % 3) * GSTAGE;
        const uint32_t sb = sa + GOP_BYTES;
#pragma unroll
        for (int kc = 0; kc < 4; kc++) {
            const int kcb = kc * 32;       // byte offset of 16-half k-slice
            uint32_t a[2][4], b[8][2];
#pragma unroll
            for (int mf = 0; mf < 2; mf++) {
                uint32_t ad = sa + (uint32_t)((mbase + mf * 16 + (mi & 1) * 8 + ri) * GROWB
                                              + kcb + (mi >> 1) * 16);
                ldsm4(a[mf][0], a[mf][1], a[mf][2], a[mf][3], ad);
            }
#pragma unroll
            for (int np = 0; np < 4; np++) {
                uint32_t bd = sb + (uint32_t)((nbase + np * 16 + (mi >> 1) * 8 + ri) * GROWB
                                              + kcb + (mi & 1) * 16);
                uint32_t r0, r1, r2, r3;
                ldsm4(r0, r1, r2, r3, bd);
                b[2 * np][0] = r0; b[2 * np][1] = r1;
                b[2 * np + 1][0] = r2; b[2 * np + 1][1] = r3;
            }
#pragma unroll
            for (int mf = 0; mf < 2; mf++)
#pragma unroll
                for (int nf = 0; nf < 8; nf++)
                    mma_f16(acc[mf][nf], a[mf], b[nf][0], b[nf][1]);
        }
    }

#pragma unroll
    for (int mf = 0; mf < 2; mf++) {
#pragma unroll
        for (int er = 0; er < 2; er++) {
            int r = rowBase + mbase + mf * 16 + qg + er * 8;
            if (MODE == 0) {
                int bi = r / Nt;
                int n = r - bi * Nt;
#pragma unroll
                for (int nf = 0; nf < 8; nf++) {
                    int cidx = colBase + nbase + nf * 8 + 2 * qt;
                    float v0 = acc[mf][nf][er * 2 + 0] + bias[cidx];
                    float v1 = acc[mf][nf][er * 2 + 1] + bias[cidx + 1];
                    int three = cidx / DIMX;
                    int rem = cidx - three * DIMX;
                    int h = rem >> 6, d = rem & 63;
                    if (three == 0) {           // q: pre-scale into exp2 domain
                        v0 *= SCALE_LOG2E;
                        v1 *= SCALE_LOG2E;
                    }
                    __half* dst = (three == 0) ? g_q : (three == 1) ? g_k : g_v;
                    *(__half2*)(dst + (((size_t)bi * NHEADS + h) * NTOTAL + (n_off + n)) * HDIM + d)
                        = __floats2half2_rn(v0, v1);
                }
            } else {
#pragma unroll
                for (int nf = 0; nf < 8; nf++) {
                    int cidx = colBase + nbase + nf * 8 + 2 * qt;
                    float v0 = acc[mf][nf][er * 2 + 0] + bias[cidx];
                    float v1 = acc[mf][nf][er * 2 + 1] + bias[cidx + 1];
                    *(float2*)(outf + (size_t)r * DIMX + cidx) = make_float2(v0, v1);
                }
            }
        }
    }
}

// ======================= fp16 flash attention (unchanged from R15) ==========
#define AROWB 144
#define AQ_BYTES  (128 * AROWB)
#define AKV_BYTES (64 * AROWB)
#define ANT      (NTOTAL / 64)        // 36 tiles
#define ATT_SMEM (AQ_BYTES + 6 * AKV_BYTES)   // 73728

__global__ __launch_bounds__(256, 2) void attn_h_kernel()
{
    extern __shared__ char dsm[];
    const uint32_t Qb = s2u(dsm);
    const uint32_t KV0 = Qb + AQ_BYTES;

    const int tid = threadIdx.x;
    const int w = tid >> 5, lane = tid & 31;
    const int qg = lane >> 2, qt = lane & 3;
    const int mi = lane >> 3, ri = lane & 7;
    const int h = blockIdx.y, bi = blockIdx.z;
    const size_t headbase = ((size_t)bi * NHEADS + h) * NTOTAL;
    const int qbase = blockIdx.x * 128;
    const int mrow = w * 16;

    auto issue_tile = [&](int t) {
        if (t < ANT) {
            const int jt = t * 64;
            const uint32_t kb = KV0 + (uint32_t)(t % 3) * (2 * AKV_BYTES);
            const uint32_t vb = kb + AKV_BYTES;
#pragma unroll
            for (int i = 0; i < 2; i++) {
                int slot = tid + i * 256;
                int r = slot >> 3, ch = slot & 7;
                uint32_t off = (uint32_t)(r * AROWB + ch * 16);
                cp16(kb + off, g_k + (headbase + jt + r) * HDIM + ch * 8);
                cp16(vb + off, g_v + (headbase + jt + r) * HDIM + ch * 8);
            }
        }
        CP_COMMIT();
    };

    issue_tile(0);
    issue_tile(1);

    {
        __half* Qp = (__half*)dsm;
#pragma unroll
        for (int i = 0; i < 4; i++) {
            int slot = tid + i * 256;
            int r = slot >> 3, ch = slot & 7;
            uint4 t = *(const uint4*)(g_q + (headbase + qbase + r) * HDIM + ch * 8);
            *(uint4*)(Qp + r * 72 + ch * 8) = t;
        }
    }
    __syncthreads();

    uint32_t qf[4][4];
#pragma unroll
    for (int kf = 0; kf < 4; kf++) {
        uint32_t ad = Qb + (uint32_t)((mrow + (mi & 1) * 8 + ri) * AROWB
                                      + kf * 32 + (mi >> 1) * 16);
        ldsm4(qf[kf][0], qf[kf][1], qf[kf][2], qf[kf][3], ad);
    }

    float of[8][4];
#pragma unroll
    for (int nf = 0; nf < 8; nf++)
#pragma unroll
        for (int e = 0; e < 4; e++) of[nf][e] = 0.f;
    float m0 = -1e30f, m1 = -1e30f, l0 = 0.f, l1 = 0.f;

    for (int t = 0; t < ANT; t++) {
        CP_WAIT1();
        __syncthreads();
        issue_tile(t + 2);

        const uint32_t Kc = KV0 + (uint32_t)(t % 3) * (2 * AKV_BYTES);
        const uint32_t Vc = Kc + AKV_BYTES;

        float sf[8][4];
#pragma unroll
        for (int nf = 0; nf < 8; nf++)
#pragma unroll
            for (int e = 0; e < 4; e++) sf[nf][e] = 0.f;
#pragma unroll
        for (int kf = 0; kf < 4; kf++) {
            const int dcb = kf * 32;
#pragma unroll
            for (int np = 0; np < 4; np++) {
                uint32_t kd = Kc + (uint32_t)((np * 16 + (mi >> 1) * 8 + ri) * AROWB
                                              + dcb + (mi & 1) * 16);
                uint32_t r0, r1, r2, r3;
                ldsm4(r0, r1, r2, r3, kd);
                mma_f16(sf[2 * np], qf[kf], r0, r1);
                mma_f16(sf[2 * np + 1], qf[kf], r2, r3);
            }
        }

        float mx0 = -1e30f, mx1 = -1e30f;
#pragma unroll
        for (int nf = 0; nf < 8; nf++) {
            mx0 = fmaxf(mx0, fmaxf(sf[nf][0], sf[nf][1]));
            mx1 = fmaxf(mx1, fmaxf(sf[nf][2], sf[nf][3]));
        }
        mx0 = fmaxf(mx0, __shfl_xor_sync(0xffffffffu, mx0, 1));
        mx0 = fmaxf(mx0, __shfl_xor_sync(0xffffffffu, mx0, 2));
        mx1 = fmaxf(mx1, __shfl_xor_sync(0xffffffffu, mx1, 1));
        mx1 = fmaxf(mx1, __shfl_xor_sync(0xffffffffu, mx1, 2));

        unsigned ball = __ballot_sync(0xffffffffu, (mx0 <= m0) && (mx1 <= m1));
        if (ball != 0xffffffffu) {
            float nm0 = fmaxf(m0, mx0), nm1 = fmaxf(m1, mx1);
            float corr0 = ex2(m0 - nm0), corr1 = ex2(m1 - nm1);
#pragma unroll
            for (int nf = 0; nf < 8; nf++) {
                of[nf][0] *= corr0; of[nf][1] *= corr0;
                of[nf][2] *= corr1; of[nf][3] *= corr1;
            }
            l0 *= corr0; l1 *= corr1;
            m0 = nm0; m1 = nm1;
        }

        float s0 = 0.f, s1 = 0.f;
        uint32_t pfrag[4][4];
#pragma unroll
        for (int nf = 0; nf < 8; nf++) {
            __half2 e01 = h2exp2(__floats2half2_rn(sf[nf][0] - m0, sf[nf][1] - m0));
            __half2 e23 = h2exp2(__floats2half2_rn(sf[nf][2] - m1, sf[nf][3] - m1));
            float2 f01 = __half22float2(e01);
            float2 f23 = __half22float2(e23);
            s0 += f01.x + f01.y;
            s1 += f23.x + f23.y;
            pfrag[nf >> 1][((nf & 1) << 1) + 0] = *reinterpret_cast<uint32_t*>(&e01);
            pfrag[nf >> 1][((nf & 1) << 1) + 1] = *reinterpret_cast<uint32_t*>(&e23);
        }
        s0 += __shfl_xor_sync(0xffffffffu, s0, 1);
        s0 += __shfl_xor_sync(0xffffffffu, s0, 2);
        s1 += __shfl_xor_sync(0xffffffffu, s1, 1);
        s1 += __shfl_xor_sync(0xffffffffu, s1, 2);
        l0 += s0; l1 += s1;

#pragma unroll
        for (int jc = 0; jc < 4; jc++) {
#pragma unroll
            for (int np = 0; np < 4; np++) {
                uint32_t vd = Vc + (uint32_t)((jc * 16 + (mi & 1) * 8 + ri) * AROWB
                                              + np * 32 + (mi >> 1) * 16);
                uint32_t r0, r1, r2, r3;
                ldsm4t(r0, r1, r2, r3, vd);
                mma_f16(of[2 * np], pfrag[jc], r0, r1);
                mma_f16(of[2 * np + 1], pfrag[jc], r2, r3);
            }
        }
    }

    const float inv0 = 1.f / l0, inv1 = 1.f / l1;
    const int row0 = qbase + mrow + qg, row1 = row0 + 8;
#pragma unroll
    for (int nf = 0; nf < 8; nf++) {
        int col = nf * 8 + 2 * qt;
        *(__half2*)(g_o + (headbase + row0) * HDIM + col)
            = __floats2half2_rn(of[nf][0] * inv0, of[nf][1] * inv0);
        *(__half2*)(g_o + (headbase + row1) * HDIM + col)
            = __floats2half2_rn(of[nf][2] * inv1, of[nf][3] * inv1);
    }
}

// ---------------------------------------------------------------------------
extern "C" void kernel_launch(void* const* d_in, const int* in_sizes, int n_in,
                              void* d_out, int out_size)
{
    const float* x       = (const float*)d_in[0];
    const float* c       = (const float*)d_in[1];
    const float* Wqkv_x  = (const float*)d_in[2];
    const float* bqkv_x  = (const float*)d_in[3];
    const float* Wqkv_c  = (const float*)d_in[4];
    const float* bqkv_c  = (const float*)d_in[5];
    const float* Wproj_x = (const float*)d_in[6];
    const float* bproj_x = (const float*)d_in[7];
    const float* Wproj_c = (const float*)d_in[8];
    const float* bproj_c = (const float*)d_in[9];
    float* out = (float*)d_out;

    cudaFuncSetAttribute(gemm_h_kernel<0>,
                         cudaFuncAttributeMaxDynamicSharedMemorySize, GEMM_SMEM);
    cudaFuncSetAttribute(gemm_h_kernel<1>,
                         cudaFuncAttributeMaxDynamicSharedMemorySize, GEMM_SMEM);
    cudaFuncSetAttribute(attn_h_kernel,
                         cudaFuncAttributeMaxDynamicSharedMemorySize, ATT_SMEM);

    __half *hx, *hc, *hWqx, *hWqc, *hWpx, *hWpc;
    cudaGetSymbolAddress((void**)&hx,   g_hx);
    cudaGetSymbolAddress((void**)&hc,   g_hc);
    cudaGetSymbolAddress((void**)&hWqx, g_hWqx);
    cudaGetSymbolAddress((void**)&hWqc, g_hWqc);
    cudaGetSymbolAddress((void**)&hWpx, g_hWpx);
    cudaGetSymbolAddress((void**)&hWpc, g_hWpc);

    f2h_all_kernel<<<(F4_TOT + 255) / 256, 256>>>(x, c, Wqkv_x, Wqkv_c, Wproj_x, Wproj_c);

    gemm_h_kernel<0><<<dim3(QKVD / 128, (BB * NXX) / 128 + (BB * NCC) / 128),
                       256, GEMM_SMEM>>>(
        hx, hc, hWqx, hWqc, bqkv_x, bqkv_c, nullptr, (BB * NXX) / 128);

    attn_h_kernel<<<dim3(NTOTAL / 128, NHEADS, BB), 256, ATT_SMEM>>>();

    gemm_h_kernel<1><<<dim3(DIMX / 128, (BB * NXX) / 128 + (BB * NCC) / 128),
                       256, GEMM_SMEM>>>(
        nullptr, nullptr, hWpx, hWpc, bproj_x, bproj_c, out, (BB * NXX) / 128);
}